// round 13
// baseline (speedup 1.0000x reference)
#include <cuda_runtime.h>
#include <cuda_bf16.h>

// AUGRU, B=65536, T=50, E=10.
// R12: occupancy fix. R11 passed at 303us but ptxas used 255 regs ->
// 2 blocks/SM (8 warps), issue=36.9%, latency-bound. This round:
//  - __launch_bounds__(128, 4): cap 128 regs -> 16 warps/SM, one full wave.
//  - Shrink live state so the cap doesn't spill: attention loaded per-step
//    immediately before the epilogue (its only use) instead of per-chunk.
//  - Otherwise the proven R11 structure: folded weights (9->6 matvecs/step)
//    in smem with 80B contiguous rows (LDS.128), scalar fmaf everywhere,
//    accurate EX2/RCP activations, 2-step 80B float4 x chunks.

#define NB 65536
#define NT 50
#define NE 10
#define TPB 128
#define NBLK (NB / TPB)   // 512 blocks

// Folded params, 630 floats:
//  [0,600):  sW[g][j][i]  (g gate, j output col, i stacked input row:
//            i 0..9 = x-side A_g = W1x_g @ W2_g, i 10..19 = h-side B_g)
//  [600,630): bias c[g][j] = b1_g @ W2_g + b2_g
__device__ __align__(16) float g_fold[630];

// ---------------------------------------------------------------- fold kernel
__global__ void fold_k(
    const float* __restrict__ Wi_r, const float* __restrict__ bi_r,
    const float* __restrict__ Wh_r, const float* __restrict__ Ws_r,
    const float* __restrict__ bs_r,
    const float* __restrict__ Wi_z, const float* __restrict__ bi_z,
    const float* __restrict__ Wh_z, const float* __restrict__ Ws_z,
    const float* __restrict__ bs_z,
    const float* __restrict__ Wi_h, const float* __restrict__ bi_h,
    const float* __restrict__ Wh_h, const float* __restrict__ Wt_h,
    const float* __restrict__ bt_h)
{
    for (int idx = threadIdx.x; idx < 630; idx += blockDim.x) {
        if (idx < 600) {
            int g = idx / 200;
            int r = idx % 200;
            int j = r / 20;
            int i = r % 20;
            const float* w2 = (g == 0) ? Ws_r : (g == 1) ? Ws_z : Wt_h;
            const float* w1;
            if (i < 10) {
                const float* wx = (g == 0) ? Wi_r : (g == 1) ? Wi_z : Wi_h;
                w1 = wx + i * 10;
            } else {
                const float* wh = (g == 0) ? Wh_r : (g == 1) ? Wh_z : Wh_h;
                w1 = wh + (i - 10) * 10;
            }
            float s = 0.0f;
#pragma unroll
            for (int k = 0; k < 10; k++) s += w1[k] * w2[k * 10 + j];
            g_fold[idx] = s;                     // sW[g*200 + j*20 + i]
        } else {
            int r = idx - 600;
            int g = r / 10;
            int j = r % 10;
            const float* w2 = (g == 0) ? Ws_r : (g == 1) ? Ws_z : Wt_h;
            const float* b1 = (g == 0) ? bi_r : (g == 1) ? bi_z : bi_h;
            const float* b2 = (g == 0) ? bs_r : (g == 1) ? bs_z : bt_h;
            float s = b2[j];
#pragma unroll
            for (int k = 0; k < 10; k++) s += b1[k] * w2[k * 10 + j];
            g_fold[idx] = s;                     // sC[g*10 + j]
        }
    }
}

// ---------------------------------------------------------------- activations
__device__ __forceinline__ float sigf(float u) {
    float e = __expf(-u);                 // FMUL + MUFU.EX2
    return __fdividef(1.0f, 1.0f + e);    // FADD + MUFU.RCP + FMUL
}
__device__ __forceinline__ float tanhfast(float u) {
    float e = __expf(2.0f * u);           // saturates correctly at +-inf
    return 1.0f - __fdividef(2.0f, e + 1.0f);
}

// ---------------------------------------------------------------- one gate
// o[j] = act( c[g][j] + sum_{i<10} x[i]*W[g][j][i] + sum_{i<10} v[i]*W[g][j][10+i] )
template <int ACT, int G>
__device__ __forceinline__ void gate1(
    const float* __restrict__ sW, const float* __restrict__ sC,
    const float (&x)[10], const float (&v)[10], float (&o)[10])
{
#pragma unroll
    for (int j = 0; j < 10; j++) {
        float acc = sC[G * 10 + j];
#pragma unroll
        for (int i = 0; i < 20; i++) {
            float w  = sW[G * 200 + j * 20 + i];
            float xi = (i < 10) ? x[i] : v[i - 10];   // compile-time select
            acc = fmaf(xi, w, acc);
        }
        o[j] = (ACT == 0) ? sigf(acc) : tanhfast(acc);
    }
}

// ---------------------------------------------------------------- one timestep
// S: which half of the 2-step x chunk. Attention is loaded HERE, right before
// its only use (epilogue), to keep it out of the live set during the gates.
// Step offset 0: 16B-aligned -> f4,f4,f2 ; offset 40B: f2,f4,f4.
template <int S>
__device__ __forceinline__ void do_step(
    const float* __restrict__ sW, const float* __restrict__ sC,
    const float (&xc)[20], const float* __restrict__ arow,  // global, chunk base
    float (&h)[10])
{
    float x[10];
#pragma unroll
    for (int k = 0; k < 10; k++) x[k] = xc[S * 10 + k];

    float r[10], z[10];
    gate1<0, 0>(sW, sC, x, h, r);       // r = sigma(xA_r + hB_r + c_r)
    gate1<0, 1>(sW, sC, x, h, z);       // z = sigma(xA_z + hB_z + c_z)

    float q[10];
#pragma unroll
    for (int k = 0; k < 10; k++) q[k] = h[k] * z[k];

    float hc[10];
    gate1<1, 2>(sW, sC, x, q, hc);      // hc = tanh(xA_h + (h.z)B_h + c_h)

    // attention for this step (aligned vector loads from global)
    float a[10];
    if (S == 0) {
        float4 v0 = __ldg((const float4*)(arow + 0));
        float4 v1 = __ldg((const float4*)(arow + 4));
        float2 v2 = __ldg((const float2*)(arow + 8));
        a[0]=v0.x; a[1]=v0.y; a[2]=v0.z; a[3]=v0.w;
        a[4]=v1.x; a[5]=v1.y; a[6]=v1.z; a[7]=v1.w;
        a[8]=v2.x; a[9]=v2.y;
    } else {
        float2 v0 = __ldg((const float2*)(arow + 10));
        float4 v1 = __ldg((const float4*)(arow + 12));
        float4 v2 = __ldg((const float4*)(arow + 16));
        a[0]=v0.x; a[1]=v0.y;
        a[2]=v1.x; a[3]=v1.y; a[4]=v1.z; a[5]=v1.w;
        a[6]=v2.x; a[7]=v2.y; a[8]=v2.z; a[9]=v2.w;
    }

#pragma unroll
    for (int k = 0; k < 10; k++) {
        float Ra = a[k] * r[k];
        h[k] = fmaf(Ra, hc[k] - h[k], h[k]);   // h + Ra*(hc-h)
    }
}

// ---------------------------------------------------------------- scan kernel
__global__ void __launch_bounds__(TPB, 4) scan_k(
    const float* __restrict__ X, const float* __restrict__ Aatt,
    const float* __restrict__ H0, float* __restrict__ O)
{
    __shared__ __align__(16) float sF[630];
    for (int i = threadIdx.x; i < 630; i += TPB) sF[i] = g_fold[i];
    __syncthreads();
    const float* sW = sF;
    const float* sC = sF + 600;

    const int e = blockIdx.x * TPB + threadIdx.x;

    const float4* xq = (const float4*)(X + (size_t)e * (NT * NE));
    const float*  ar = Aatt + (size_t)e * (NT * NE);

    float h[10];
#pragma unroll
    for (int k = 0; k < 10; k++) h[k] = __ldg(H0 + k);   // broadcast init

#pragma unroll 1
    for (int c = 0; c < NT / 2; c++) {   // 2 steps/chunk: 80B = 5 aligned float4
        float xc[20];
#pragma unroll
        for (int q = 0; q < 5; q++) {
            float4 v = __ldg(xq + c * 5 + q);
            xc[4 * q + 0] = v.x; xc[4 * q + 1] = v.y;
            xc[4 * q + 2] = v.z; xc[4 * q + 3] = v.w;
        }
        const float* arow = ar + c * 20;
        do_step<0>(sW, sC, xc, arow, h);
        do_step<1>(sW, sC, xc, arow, h);
    }

    // write h_final [B, E]
    float2* op = (float2*)(O + (size_t)e * NE);
#pragma unroll
    for (int k = 0; k < 5; k++) op[k] = make_float2(h[2 * k], h[2 * k + 1]);
}

// ---------------------------------------------------------------- launch
extern "C" void kernel_launch(void* const* d_in, const int* in_sizes, int n_in,
                              void* d_out, int out_size)
{
    const float* X  = (const float*)d_in[0];
    const float* Aa = (const float*)d_in[1];
    const float* H0 = (const float*)d_in[2];

    fold_k<<<1, 256>>>(
        (const float*)d_in[3],  (const float*)d_in[4],  (const float*)d_in[5],
        (const float*)d_in[6],  (const float*)d_in[7],
        (const float*)d_in[8],  (const float*)d_in[9],  (const float*)d_in[10],
        (const float*)d_in[11], (const float*)d_in[12],
        (const float*)d_in[13], (const float*)d_in[14], (const float*)d_in[15],
        (const float*)d_in[16], (const float*)d_in[17]);

    scan_k<<<NBLK, TPB>>>(X, Aa, H0, (float*)d_out);
}

// round 14
// speedup vs baseline: 1.5044x; 1.5044x over previous
#include <cuda_runtime.h>
#include <cuda_bf16.h>

// AUGRU, B=65536, T=50, E=10.
// R13: occupancy, take two. R11 = 255 regs / 8 warps/SM / issue 37% / 303us.
// R12 capped at 128 regs -> ptxas SPILLED (DRAM 38%, 3GB traffic, 1011us).
// The body genuinely needs ~170 live regs when unrolled. So:
//  - __launch_bounds__(TPB, 3): 168 regs -> 12 warps/SM (3/SMSP), no spill.
//  - Trim real live state: BOTH x and attention are loaded per-step right
//    before first use (no 2-step chunk buffers held across gates).
//  - Proven R11 math core: folded weights (9 -> 6 matvecs/step) in smem with
//    80B contiguous rows (LDS.128), scalar fmaf, accurate EX2/RCP activations.

#define NB 65536
#define NT 50
#define NE 10
#define TPB 128
#define NBLK (NB / TPB)   // 512 blocks

// Folded params, 630 floats:
//  [0,600):  sW[g][j][i]  (g gate, j output col, i stacked input row:
//            i 0..9 = x-side A_g = W1x_g @ W2_g, i 10..19 = h-side B_g)
//  [600,630): bias c[g][j] = b1_g @ W2_g + b2_g
__device__ __align__(16) float g_fold[630];

// ---------------------------------------------------------------- fold kernel
__global__ void fold_k(
    const float* __restrict__ Wi_r, const float* __restrict__ bi_r,
    const float* __restrict__ Wh_r, const float* __restrict__ Ws_r,
    const float* __restrict__ bs_r,
    const float* __restrict__ Wi_z, const float* __restrict__ bi_z,
    const float* __restrict__ Wh_z, const float* __restrict__ Ws_z,
    const float* __restrict__ bs_z,
    const float* __restrict__ Wi_h, const float* __restrict__ bi_h,
    const float* __restrict__ Wh_h, const float* __restrict__ Wt_h,
    const float* __restrict__ bt_h)
{
    for (int idx = threadIdx.x; idx < 630; idx += blockDim.x) {
        if (idx < 600) {
            int g = idx / 200;
            int r = idx % 200;
            int j = r / 20;
            int i = r % 20;
            const float* w2 = (g == 0) ? Ws_r : (g == 1) ? Ws_z : Wt_h;
            const float* w1;
            if (i < 10) {
                const float* wx = (g == 0) ? Wi_r : (g == 1) ? Wi_z : Wi_h;
                w1 = wx + i * 10;
            } else {
                const float* wh = (g == 0) ? Wh_r : (g == 1) ? Wh_z : Wh_h;
                w1 = wh + (i - 10) * 10;
            }
            float s = 0.0f;
#pragma unroll
            for (int k = 0; k < 10; k++) s += w1[k] * w2[k * 10 + j];
            g_fold[idx] = s;                     // sW[g*200 + j*20 + i]
        } else {
            int r = idx - 600;
            int g = r / 10;
            int j = r % 10;
            const float* w2 = (g == 0) ? Ws_r : (g == 1) ? Ws_z : Wt_h;
            const float* b1 = (g == 0) ? bi_r : (g == 1) ? bi_z : bi_h;
            const float* b2 = (g == 0) ? bs_r : (g == 1) ? bs_z : bt_h;
            float s = b2[j];
#pragma unroll
            for (int k = 0; k < 10; k++) s += b1[k] * w2[k * 10 + j];
            g_fold[idx] = s;                     // sC[g*10 + j]
        }
    }
}

// ---------------------------------------------------------------- activations
__device__ __forceinline__ float sigf(float u) {
    float e = __expf(-u);                 // FMUL + MUFU.EX2
    return __fdividef(1.0f, 1.0f + e);    // FADD + MUFU.RCP + FMUL
}
__device__ __forceinline__ float tanhfast(float u) {
    float e = __expf(2.0f * u);           // saturates correctly at +-inf
    return 1.0f - __fdividef(2.0f, e + 1.0f);
}

// ---------------------------------------------------------------- 10-float step load
// Loads one step's 10 floats from a row base whose step offset is 0 or 40B.
// Offset 0 (16B aligned): f4,f4,f2.  Offset 40B: f2,f4,f4.
template <int S>
__device__ __forceinline__ void load10(const float* __restrict__ p, float (&a)[10]) {
    if (S == 0) {
        float4 v0 = __ldg((const float4*)(p + 0));
        float4 v1 = __ldg((const float4*)(p + 4));
        float2 v2 = __ldg((const float2*)(p + 8));
        a[0]=v0.x; a[1]=v0.y; a[2]=v0.z; a[3]=v0.w;
        a[4]=v1.x; a[5]=v1.y; a[6]=v1.z; a[7]=v1.w;
        a[8]=v2.x; a[9]=v2.y;
    } else {
        float2 v0 = __ldg((const float2*)(p + 10));
        float4 v1 = __ldg((const float4*)(p + 12));
        float4 v2 = __ldg((const float4*)(p + 16));
        a[0]=v0.x; a[1]=v0.y;
        a[2]=v1.x; a[3]=v1.y; a[4]=v1.z; a[5]=v1.w;
        a[6]=v2.x; a[7]=v2.y; a[8]=v2.z; a[9]=v2.w;
    }
}

// ---------------------------------------------------------------- one gate
// o[j] = act( c[g][j] + sum_{i<10} x[i]*W[g][j][i] + sum_{i<10} v[i]*W[g][j][10+i] )
template <int ACT, int G>
__device__ __forceinline__ void gate1(
    const float* __restrict__ sW, const float* __restrict__ sC,
    const float (&x)[10], const float (&v)[10], float (&o)[10])
{
#pragma unroll
    for (int j = 0; j < 10; j++) {
        float acc = sC[G * 10 + j];
#pragma unroll
        for (int i = 0; i < 20; i++) {
            float w  = sW[G * 200 + j * 20 + i];
            float xi = (i < 10) ? x[i] : v[i - 10];   // compile-time select
            acc = fmaf(xi, w, acc);
        }
        o[j] = (ACT == 0) ? sigf(acc) : tanhfast(acc);
    }
}

// ---------------------------------------------------------------- one timestep
// xrow/arow point at this CHUNK's base in global; S picks the 0/40B half.
template <int S>
__device__ __forceinline__ void do_step(
    const float* __restrict__ sW, const float* __restrict__ sC,
    const float* __restrict__ xrow, const float* __restrict__ arow,
    float (&h)[10])
{
    float x[10];
    load10<S>(xrow, x);

    float r[10], z[10];
    gate1<0, 0>(sW, sC, x, h, r);       // r = sigma(xA_r + hB_r + c_r)
    gate1<0, 1>(sW, sC, x, h, z);       // z = sigma(xA_z + hB_z + c_z)

    float q[10];
#pragma unroll
    for (int k = 0; k < 10; k++) q[k] = h[k] * z[k];

    float hc[10];
    gate1<1, 2>(sW, sC, x, q, hc);      // hc = tanh(xA_h + (h.z)B_h + c_h)

    float a[10];
    load10<S>(arow, a);                 // loaded right before its only use

#pragma unroll
    for (int k = 0; k < 10; k++) {
        float Ra = a[k] * r[k];
        h[k] = fmaf(Ra, hc[k] - h[k], h[k]);   // h + Ra*(hc-h)
    }
}

// ---------------------------------------------------------------- scan kernel
__global__ void __launch_bounds__(TPB, 3) scan_k(
    const float* __restrict__ X, const float* __restrict__ Aatt,
    const float* __restrict__ H0, float* __restrict__ O)
{
    __shared__ __align__(16) float sF[630];
    for (int i = threadIdx.x; i < 630; i += TPB) sF[i] = g_fold[i];
    __syncthreads();
    const float* sW = sF;
    const float* sC = sF + 600;

    const int e = blockIdx.x * TPB + threadIdx.x;

    const float* xr = X    + (size_t)e * (NT * NE);
    const float* ar = Aatt + (size_t)e * (NT * NE);

    float h[10];
#pragma unroll
    for (int k = 0; k < 10; k++) h[k] = __ldg(H0 + k);   // broadcast init

#pragma unroll 1
    for (int c = 0; c < NT / 2; c++) {   // 2 steps per chunk (alignment parity)
        const float* xrow = xr + c * 20;
        const float* arow = ar + c * 20;
        do_step<0>(sW, sC, xrow, arow, h);
        do_step<1>(sW, sC, xrow, arow, h);
    }

    // write h_final [B, E]
    float2* op = (float2*)(O + (size_t)e * NE);
#pragma unroll
    for (int k = 0; k < 5; k++) op[k] = make_float2(h[2 * k], h[2 * k + 1]);
}

// ---------------------------------------------------------------- launch
extern "C" void kernel_launch(void* const* d_in, const int* in_sizes, int n_in,
                              void* d_out, int out_size)
{
    const float* X  = (const float*)d_in[0];
    const float* Aa = (const float*)d_in[1];
    const float* H0 = (const float*)d_in[2];

    fold_k<<<1, 256>>>(
        (const float*)d_in[3],  (const float*)d_in[4],  (const float*)d_in[5],
        (const float*)d_in[6],  (const float*)d_in[7],
        (const float*)d_in[8],  (const float*)d_in[9],  (const float*)d_in[10],
        (const float*)d_in[11], (const float*)d_in[12],
        (const float*)d_in[13], (const float*)d_in[14], (const float*)d_in[15],
        (const float*)d_in[16], (const float*)d_in[17]);

    scan_k<<<NBLK, TPB>>>(X, Aa, H0, (float*)d_out);
}

// round 15
// speedup vs baseline: 1.5810x; 1.0510x over previous
#include <cuda_runtime.h>
#include <cuda_bf16.h>

// AUGRU, B=65536, T=50, E=10.
// R14: back to the proven no-spill compilation point (255 regs, 8 warps/SM;
// R12/R13 proved any tighter cap spills), and shrink the instruction stream:
// all matvec math is fma.rn.f32x2 on PERSISTENTLY packed u64 registers.
// R5/R7 died from per-op mov.b64 pack/unpack temporaries (7 .b64 temps per
// asm block); here h/x/a/q/acc live as u64 pairs end-to-end, weights are read
// as ulonglong2 (same LDS.128 as scalar), and the only pack/unpack is at the
// 30 activations. ~690 inst/step vs 945 scalar.

#define NB 65536
#define NT 50
#define NE 10
#define TPB 128
#define NBLK (NB / TPB)   // 512 blocks

typedef unsigned long long ull;

// Folded params, 630 floats (layout unchanged from R11):
//  [0,600):  sW[g][j][i]  (i 0..9 = x-side A_g = W1x_g@W2_g, 10..19 = h-side B_g)
//            each j-row = 20 floats = 80B, 16B-aligned -> 5 x ulonglong2
//  [600,630): bias c[g][j] = b1_g@W2_g + b2_g
__device__ __align__(16) float g_fold[630];

// ---------------------------------------------------------------- fold kernel
__global__ void fold_k(
    const float* __restrict__ Wi_r, const float* __restrict__ bi_r,
    const float* __restrict__ Wh_r, const float* __restrict__ Ws_r,
    const float* __restrict__ bs_r,
    const float* __restrict__ Wi_z, const float* __restrict__ bi_z,
    const float* __restrict__ Wh_z, const float* __restrict__ Ws_z,
    const float* __restrict__ bs_z,
    const float* __restrict__ Wi_h, const float* __restrict__ bi_h,
    const float* __restrict__ Wh_h, const float* __restrict__ Wt_h,
    const float* __restrict__ bt_h)
{
    for (int idx = threadIdx.x; idx < 630; idx += blockDim.x) {
        if (idx < 600) {
            int g = idx / 200;
            int r = idx % 200;
            int j = r / 20;
            int i = r % 20;
            const float* w2 = (g == 0) ? Ws_r : (g == 1) ? Ws_z : Wt_h;
            const float* w1;
            if (i < 10) {
                const float* wx = (g == 0) ? Wi_r : (g == 1) ? Wi_z : Wi_h;
                w1 = wx + i * 10;
            } else {
                const float* wh = (g == 0) ? Wh_r : (g == 1) ? Wh_z : Wh_h;
                w1 = wh + (i - 10) * 10;
            }
            float s = 0.0f;
#pragma unroll
            for (int k = 0; k < 10; k++) s += w1[k] * w2[k * 10 + j];
            g_fold[idx] = s;                     // sW[g*200 + j*20 + i]
        } else {
            int r = idx - 600;
            int g = r / 10;
            int j = r % 10;
            const float* w2 = (g == 0) ? Ws_r : (g == 1) ? Ws_z : Wt_h;
            const float* b1 = (g == 0) ? bi_r : (g == 1) ? bi_z : bi_h;
            const float* b2 = (g == 0) ? bs_r : (g == 1) ? bs_z : bt_h;
            float s = b2[j];
#pragma unroll
            for (int k = 0; k < 10; k++) s += b1[k] * w2[k * 10 + j];
            g_fold[idx] = s;                     // sC[g*10 + j]
        }
    }
}

// ---------------------------------------------------------------- f32x2 (clean)
// No internal temporaries: operands are persistent u64 registers.
__device__ __forceinline__ ull f2fma(ull a, ull b, ull c) {
    ull d;
    asm("fma.rn.f32x2 %0, %1, %2, %3;" : "=l"(d) : "l"(a), "l"(b), "l"(c));
    return d;
}
__device__ __forceinline__ ull f2mul(ull a, ull b) {
    ull d;
    asm("mul.rn.f32x2 %0, %1, %2;" : "=l"(d) : "l"(a), "l"(b));
    return d;
}
__device__ __forceinline__ ull pk2(float lo, float hi) {
    ull r;
    asm("mov.b64 %0, {%1, %2};" : "=l"(r) : "f"(lo), "f"(hi));
    return r;
}
__device__ __forceinline__ void upk2(ull v, float& lo, float& hi) {
    asm("mov.b64 {%0, %1}, %2;" : "=f"(lo), "=f"(hi) : "l"(v));
}

// ---------------------------------------------------------------- activations
__device__ __forceinline__ float sigf(float u) {
    float e = __expf(-u);                 // FMUL + MUFU.EX2
    return __fdividef(1.0f, 1.0f + e);    // FADD + MUFU.RCP
}
__device__ __forceinline__ float tanhfast(float u) {
    float e = __expf(2.0f * u);           // saturates correctly at +-inf
    return 1.0f - __fdividef(2.0f, e + 1.0f);
}

// ---------------------------------------------------------------- one gate (packed)
// x = 5 input pairs (x-side), v = 5 pairs (h or h*z side), o = 5 result pairs.
// Per j: 5 x ulonglong2 weight loads (LDS.128) + 10 chained f2fma.
template <int ACT, int G>
__device__ __forceinline__ void gateP(
    const float* __restrict__ sF,
    const ull (&x)[5], const ull (&v)[5], ull (&o)[5])
{
    float res[10];
#pragma unroll
    for (int j = 0; j < 10; j++) {
        const ulonglong2* wp = (const ulonglong2*)(sF + G * 200 + j * 20);
        ulonglong2 w0 = wp[0], w1 = wp[1], w2 = wp[2], w3 = wp[3], w4 = wp[4];
        ull acc = pk2(sF[600 + G * 10 + j], 0.0f);   // bias in lane 0
        acc = f2fma(x[0], w0.x, acc);
        acc = f2fma(x[1], w0.y, acc);
        acc = f2fma(x[2], w1.x, acc);
        acc = f2fma(x[3], w1.y, acc);
        acc = f2fma(x[4], w2.x, acc);
        acc = f2fma(v[0], w2.y, acc);
        acc = f2fma(v[1], w3.x, acc);
        acc = f2fma(v[2], w3.y, acc);
        acc = f2fma(v[3], w4.x, acc);
        acc = f2fma(v[4], w4.y, acc);
        float lo, hi;
        upk2(acc, lo, hi);
        float u = lo + hi;                            // horizontal reduce
        res[j] = (ACT == 0) ? sigf(u) : tanhfast(u);
    }
#pragma unroll
    for (int k = 0; k < 5; k++) o[k] = pk2(res[2 * k], res[2 * k + 1]);
}

// ---------------------------------------------------------------- one timestep
template <int S>
__device__ __forceinline__ void do_stepP(
    const float* __restrict__ sF,
    const ull (&xc)[10], const ull (&ac)[10], ull (&h)[5])
{
    ull x[5];
#pragma unroll
    for (int k = 0; k < 5; k++) x[k] = xc[S * 5 + k];

    ull r[5], z[5];
    gateP<0, 0>(sF, x, h, r);            // r = sigma(xA_r + hB_r + c_r)
    gateP<0, 1>(sF, x, h, z);            // z = sigma(xA_z + hB_z + c_z)

    ull q[5];
#pragma unroll
    for (int k = 0; k < 5; k++) q[k] = f2mul(h[k], z[k]);

    ull hc[5];
    gateP<1, 2>(sF, x, q, hc);           // hc = tanh(xA_h + (h.z)B_h + c_h)

    const ull NEG1 = pk2(-1.0f, -1.0f);  // loop-invariant, hoisted
#pragma unroll
    for (int k = 0; k < 5; k++) {
        ull Ra = f2mul(ac[S * 5 + k], r[k]);
        ull d  = f2fma(h[k], NEG1, hc[k]);   // hc - h
        h[k]   = f2fma(Ra, d, h[k]);         // h + Ra*(hc-h)
    }
}

// ---------------------------------------------------------------- scan kernel
__global__ void __launch_bounds__(TPB, 2) scan_k(
    const float* __restrict__ X, const float* __restrict__ Aatt,
    const float* __restrict__ H0, float* __restrict__ O)
{
    __shared__ __align__(16) float sF[632];
    for (int i = threadIdx.x; i < 630; i += TPB) sF[i] = g_fold[i];
    __syncthreads();

    const int e = blockIdx.x * TPB + threadIdx.x;

    // elem row = 2000B (16B multiple); chunk = 80B = 5 x ulonglong2
    const ulonglong2* xq = (const ulonglong2*)(X    + (size_t)e * (NT * NE));
    const ulonglong2* aq = (const ulonglong2*)(Aatt + (size_t)e * (NT * NE));

    ull h[5];
#pragma unroll
    for (int k = 0; k < 5; k++)
        h[k] = pk2(__ldg(H0 + 2 * k), __ldg(H0 + 2 * k + 1));   // broadcast init

#pragma unroll 1
    for (int c = 0; c < NT / 2; c++) {   // 2 steps/chunk
        ull xc[10], ac[10];
#pragma unroll
        for (int q = 0; q < 5; q++) {
            ulonglong2 tx = xq[c * 5 + q];
            ulonglong2 ta = aq[c * 5 + q];
            xc[2 * q] = tx.x; xc[2 * q + 1] = tx.y;
            ac[2 * q] = ta.x; ac[2 * q + 1] = ta.y;
        }
        do_stepP<0>(sF, xc, ac, h);
        do_stepP<1>(sF, xc, ac, h);
    }

    // write h_final [B, E]
    float2* op = (float2*)(O + (size_t)e * NE);
#pragma unroll
    for (int k = 0; k < 5; k++) {
        float lo, hi;
        upk2(h[k], lo, hi);
        op[k] = make_float2(lo, hi);
    }
}

// ---------------------------------------------------------------- launch
extern "C" void kernel_launch(void* const* d_in, const int* in_sizes, int n_in,
                              void* d_out, int out_size)
{
    const float* X  = (const float*)d_in[0];
    const float* Aa = (const float*)d_in[1];
    const float* H0 = (const float*)d_in[2];

    fold_k<<<1, 256>>>(
        (const float*)d_in[3],  (const float*)d_in[4],  (const float*)d_in[5],
        (const float*)d_in[6],  (const float*)d_in[7],
        (const float*)d_in[8],  (const float*)d_in[9],  (const float*)d_in[10],
        (const float*)d_in[11], (const float*)d_in[12],
        (const float*)d_in[13], (const float*)d_in[14], (const float*)d_in[15],
        (const float*)d_in[16], (const float*)d_in[17]);

    scan_k<<<NBLK, TPB>>>(X, Aa, H0, (float*)d_out);
}